// round 11
// baseline (speedup 1.0000x reference)
#include <cuda_runtime.h>
#include <cstdint>

#define BB 128
#define PP 8732
#define NG (PP/4)      // 2183
#define MM 16
#define TPB 512
#define NW (TPB/32)

__device__ float g_loc[BB];
__device__ float g_conf[BB];
__device__ int   g_npos[BB];
__device__ unsigned g_ctr = 0;

__device__ __forceinline__ unsigned midp(unsigned a, unsigned b) {
    return a + ((b - a + 1u) >> 1);   // candidate in [a+1, b] when b > a
}

__global__ __launch_bounds__(TPB, 1) void multibox_kernel(
    const float* __restrict__ locs,    // (B,P,4)
    const float* __restrict__ scores,  // (B,P,3)
    const float* __restrict__ boxes,   // (B,M,4) xyxy
    const int*   __restrict__ labels,  // (B,M)
    const float* __restrict__ priors,  // (P,4) cxcy
    float* __restrict__ out, int out_size)
{
    __shared__ __align__(16) float A[PP];            // conf_neg per prior
    __shared__ __align__(4)  unsigned char sobj[PP]; // 0 | 0x80 pos | 0x40|m forced
    __shared__ float4 sbox[MM];
    __shared__ float  sarea[MM];
    __shared__ float  bcx[MM], bcy[MM], bwd[MM], bht[MM];
    __shared__ int    blab[MM];
    __shared__ unsigned long long bestkey[MM];
    __shared__ float w_f0[NW], w_f1[NW];
    __shared__ int   w_i0[NW];
    __shared__ unsigned cnt[9];                      // 3 rotating sets x 3 counters
    __shared__ float s_conf, s_loc, s_sum;
    __shared__ int   s_np, s_last;
    __shared__ unsigned s_cnt;

    const int b    = blockIdx.x;
    const int tid  = threadIdx.x;
    const int warp = tid >> 5, lane = tid & 31;

    if (tid < MM) {
        float4 bb = *(const float4*)(boxes + ((size_t)b * MM + tid) * 4);
        sbox[tid] = bb;
        sarea[tid] = (bb.z - bb.x) * (bb.w - bb.y);
        bcx[tid] = (bb.x + bb.z) * 0.5f;
        bcy[tid] = (bb.y + bb.w) * 0.5f;
        bwd[tid] = bb.z - bb.x;
        bht[tid] = bb.w - bb.y;
        blab[tid] = labels[b * MM + tid];
        bestkey[tid] = 0ull;
    }
    if (tid < 9) cnt[tid] = 0u;
    __syncthreads();

    // ===== Phase 1: two sweeps of 8 objects, boxes in registers.          =====
    // Per prior we only need: (a) pos = any_m(iou_m >= 0.5) <=> 3*inter >= S
    //                         (b) per-object argmax over p (exact rational).
    // The per-prior argmax (which object) is recomputed in phase 3 for the
    // sparse positives only.
    {
        unsigned posmask = 0;               // bit i: prior tid + i*TPB is positive
#pragma unroll 1
        for (int sweep = 0; sweep < 2; sweep++) {
            const int mbase = sweep * 8;
            float rx1[8], ry1[8], rx2[8], ry2[8], rsa[8];
#pragma unroll
            for (int m = 0; m < 8; m++) {
                float4 bb = sbox[mbase + m];
                rx1[m] = bb.x; ry1[m] = bb.y; rx2[m] = bb.z; ry2[m] = bb.w;
                rsa[m] = sarea[mbase + m];
            }
            float oi[8], oS[8]; int op[8];
#pragma unroll
            for (int m = 0; m < 8; m++) { oi[m] = 0.0f; oS[m] = 1.0f; op[m] = 0; }

            int i = 0;
            for (int p = tid; p < PP; p += TPB, i++) {
                float4 pr = *(const float4*)(priors + (size_t)p * 4);
                float hw = pr.z * 0.5f, hh = pr.w * 0.5f;
                float px1 = pr.x - hw, py1 = pr.y - hh;
                float px2 = pr.x + hw, py2 = pr.y + hh;
                float parea = pr.z * pr.w;
                bool pos = false;
#pragma unroll
                for (int m = 0; m < 8; m++) {
                    float w = fminf(rx2[m], px2) - fmaxf(rx1[m], px1);
                    float h = fminf(ry2[m], py2) - fmaxf(ry1[m], py1);
                    float inter = fmaxf(w, 0.0f) * fmaxf(h, 0.0f);
                    float S = rsa[m] + parea;
                    pos |= (3.0f * inter >= S);        // iou >= 0.5 exactly
                    if (inter * oS[m] > oi[m] * S) { oi[m] = inter; oS[m] = S; op[m] = p; }
                }
                if (pos) posmask |= (1u << i);
            }
            // cross-thread per-object argmax: key = (iou_bits, ~p)
#pragma unroll
            for (int m = 0; m < 8; m++) {
                float iou = __fdividef(oi[m], oS[m] - oi[m]);
                unsigned long long key =
                    ((unsigned long long)__float_as_uint(iou) << 32) |
                    (unsigned)(0xFFFFFFFFu - (unsigned)op[m]);
#pragma unroll
                for (int o = 16; o; o >>= 1) {
                    unsigned long long other = __shfl_down_sync(0xFFFFFFFFu, key, o);
                    if (other > key) key = other;
                }
                if (lane == 0) atomicMax(&bestkey[mbase + m], key);
            }
        }
        // store flags
        int i = 0;
        for (int p = tid; p < PP; p += TPB, i++)
            sobj[p] = ((posmask >> i) & 1u) ? 0x80 : 0;
    }
    __syncthreads();

    // override: prior_obj[m] forced positive with object m (sequential, last wins)
    if (tid == 0) {
        for (int m = 0; m < MM; m++) {
            unsigned p = 0xFFFFFFFFu - (unsigned)(bestkey[m] & 0xFFFFFFFFull);
            sobj[p] = (unsigned char)(0x40 | m);
        }
    }
    __syncthreads();

    // ===== Phase 3: BCE + loc-loss, 2 groups/iter for MLP, conf_neg into A =====
    float conf_pos = 0.0f, loc_sum = 0.0f;
    int npos = 0;
    const float* srow = scores + (size_t)b * PP * 3;

    auto process_group = [&](int g, float4 s0, float4 s1, float4 s2, unsigned ob4) {
        float ch0[4] = { s0.x, s0.w, s1.z, s2.y };
        float ch1[4] = { s0.y, s1.x, s1.w, s2.z };
        float ch2[4] = { s0.z, s1.y, s2.x, s2.w };
        float v[4];
#pragma unroll
        for (int j = 0; j < 4; j++) {
            unsigned obf = (ob4 >> (8 * j)) & 0xFFu;
            float x0 = ch0[j], x1 = ch1[j], x2 = ch2[j];
            float bce = fmaxf(x0, 0.0f) + __logf(1.0f + __expf(-fabsf(x0)))
                      + fmaxf(x1, 0.0f) + __logf(1.0f + __expf(-fabsf(x1)))
                      + fmaxf(x2, 0.0f) + __logf(1.0f + __expf(-fabsf(x2)));
            if (obf) {
                // positive prior
                int p = 4 * g + j;
                float4 pr = *(const float4*)(priors + (size_t)p * 4);
                int obj;
                if (obf & 0x40) {
                    obj = (int)(obf & 0x3Fu);          // forced: object known
                } else {
                    // recompute argmax_m iou (same order & compares as before)
                    float hw = pr.z * 0.5f, hh = pr.w * 0.5f;
                    float px1 = pr.x - hw, py1 = pr.y - hh;
                    float px2 = pr.x + hw, py2 = pr.y + hh;
                    float parea = pr.z * pr.w;
                    float bint = 0.0f, bS = 1.0f; obj = 0;
#pragma unroll
                    for (int m = 0; m < MM; m++) {
                        float4 bb = sbox[m];
                        float w = fminf(bb.z, px2) - fmaxf(bb.x, px1);
                        float h = fminf(bb.w, py2) - fmaxf(bb.y, py1);
                        float inter = fmaxf(w, 0.0f) * fmaxf(h, 0.0f);
                        float S = sarea[m] + parea;
                        if (inter * bS > bint * S) { bint = inter; bS = S; obj = m; }
                    }
                }
                int lab = blab[obj];
                if (lab == 1 || lab == 3) bce -= x1;
                if (lab >= 2) bce -= x2;
                conf_pos += bce;
                npos++;
                v[j] = 0.0f;
                float gx = (bcx[obj] - pr.x) * 10.0f * __fdividef(1.0f, pr.z);
                float gy = (bcy[obj] - pr.y) * 10.0f * __fdividef(1.0f, pr.w);
                float gw = __logf(__fdividef(bwd[obj], pr.z)) * 5.0f;
                float gh = __logf(__fdividef(bht[obj], pr.w)) * 5.0f;
                float4 pl = *(const float4*)(locs + ((size_t)b * PP + p) * 4);
                loc_sum += fabsf(pl.x - gx) + fabsf(pl.y - gy) +
                           fabsf(pl.z - gw) + fabsf(pl.w - gh);
            } else {
                v[j] = bce - x0;                      // negative: lab 0 target [1,0,0]
            }
        }
        ((float4*)A)[g] = make_float4(v[0], v[1], v[2], v[3]);
    };

    for (int g0 = tid; g0 < NG; g0 += 2 * TPB) {
        const int g1 = g0 + TPB;
        const bool h2 = (g1 < NG);
        const int g1c = h2 ? g1 : g0;
        const float4* sp0 = (const float4*)srow + (size_t)g0 * 3;
        const float4* sp1 = (const float4*)srow + (size_t)g1c * 3;
        float4 a0 = sp0[0], a1 = sp0[1], a2 = sp0[2];
        float4 c0 = sp1[0], c1 = sp1[1], c2 = sp1[2];
        unsigned obA = ((const unsigned*)sobj)[g0];
        unsigned obB = ((const unsigned*)sobj)[g1c];
        process_group(g0, a0, a1, a2, obA);
        if (h2) process_group(g1, c0, c1, c2, obB);
    }

    // ---- deterministic block reduce ----
#pragma unroll
    for (int o = 16; o; o >>= 1) {
        conf_pos += __shfl_down_sync(0xFFFFFFFFu, conf_pos, o);
        loc_sum  += __shfl_down_sync(0xFFFFFFFFu, loc_sum, o);
    }
    npos = __reduce_add_sync(0xFFFFFFFFu, npos);
    if (lane == 0) { w_f0[warp] = conf_pos; w_f1[warp] = loc_sum; w_i0[warp] = npos; }
    __syncthreads();
    if (tid == 0) {
        float c = 0.0f, l = 0.0f; int n = 0;
#pragma unroll
        for (int i = 0; i < NW; i++) { c += w_f0[i]; l += w_f1[i]; n += w_i0[i]; }
        s_conf = c; s_loc = l; s_np = n;
    }
    __syncthreads();

    const int npos_b = s_np;
    const unsigned K = 3u * (unsigned)npos_b;

    // ===== Phase 4: top-K sum, 4-way bisection with exact-count early exit =====
    float hard = 0.0f;
    if (K > 0) {
        unsigned lo = 0u, hi = 0x7F800000u;
        int r = 0;
        bool exact = false; unsigned tEx = 0u;
        const float4* sv4 = (const float4*)A;
        while (lo < hi) {
            unsigned c2v = midp(lo, hi);
            unsigned c1v = lo + ((c2v - lo) >> 1);
            unsigned c3v = midp(c2v, hi);
            int n1 = 0, n2 = 0, n3 = 0;
            for (int g = tid; g < NG; g += TPB) {
                float4 vv = sv4[g];
                unsigned u0 = __float_as_uint(vv.x), u1 = __float_as_uint(vv.y);
                unsigned u2 = __float_as_uint(vv.z), u3 = __float_as_uint(vv.w);
                n1 += (u0 >= c1v) + (u1 >= c1v) + (u2 >= c1v) + (u3 >= c1v);
                n2 += (u0 >= c2v) + (u1 >= c2v) + (u2 >= c2v) + (u3 >= c2v);
                n3 += (u0 >= c3v) + (u1 >= c3v) + (u2 >= c3v) + (u3 >= c3v);
            }
            n1 = __reduce_add_sync(0xFFFFFFFFu, n1);
            n2 = __reduce_add_sync(0xFFFFFFFFu, n2);
            n3 = __reduce_add_sync(0xFFFFFFFFu, n3);
            int s = (r % 3) * 3;
            if (lane == 0)      atomicAdd(&cnt[s + 0], (unsigned)n1);
            else if (lane == 1) atomicAdd(&cnt[s + 1], (unsigned)n2);
            else if (lane == 2) atomicAdd(&cnt[s + 2], (unsigned)n3);
            if (tid == 0) {
                int z = ((r + 1) % 3) * 3;
                cnt[z + 0] = 0u; cnt[z + 1] = 0u; cnt[z + 2] = 0u;
            }
            __syncthreads();
            unsigned N1 = cnt[s + 0], N2 = cnt[s + 1], N3 = cnt[s + 2];
            if (N2 == K)      { exact = true; tEx = c2v; }
            else if (N1 == K) { exact = true; tEx = c1v; }
            else if (N3 == K) { exact = true; tEx = c3v; }
            if (exact) break;           // uniform decision
            if (N2 >= K) {
                lo = c2v;
                if (hi > lo) { if (N3 >= K) lo = c3v; else hi = c3v - 1u; }
            } else {
                hi = c2v - 1u;
                if (hi > lo) { if (N1 >= K) lo = c1v; else hi = c1v - 1u; }
            }
            r++;
        }
        if (tid == 0) s_cnt = 0u;
        __syncthreads();
        if (exact) {
            float ssum = 0.0f;
            for (int g = tid; g < NG; g += TPB) {
                float4 vv = sv4[g];
                if (__float_as_uint(vv.x) >= tEx) ssum += vv.x;
                if (__float_as_uint(vv.y) >= tEx) ssum += vv.y;
                if (__float_as_uint(vv.z) >= tEx) ssum += vv.z;
                if (__float_as_uint(vv.w) >= tEx) ssum += vv.w;
            }
#pragma unroll
            for (int o = 16; o; o >>= 1)
                ssum += __shfl_down_sync(0xFFFFFFFFu, ssum, o);
            if (lane == 0) w_f0[warp] = ssum;
            __syncthreads();
            if (tid == 0) {
                float t = 0.0f;
#pragma unroll
                for (int i = 0; i < NW; i++) t += w_f0[i];
                s_sum = t;
            }
        } else {
            const float thr = __uint_as_float(lo);
            int c = 0; float ssum = 0.0f;
            for (int g = tid; g < NG; g += TPB) {
                float4 vv = sv4[g];
                if (vv.x > thr) { c++; ssum += vv.x; }
                if (vv.y > thr) { c++; ssum += vv.y; }
                if (vv.z > thr) { c++; ssum += vv.z; }
                if (vv.w > thr) { c++; ssum += vv.w; }
            }
#pragma unroll
            for (int o = 16; o; o >>= 1)
                ssum += __shfl_down_sync(0xFFFFFFFFu, ssum, o);
            c = __reduce_add_sync(0xFFFFFFFFu, c);
            if (lane == 0) { w_f0[warp] = ssum; atomicAdd(&s_cnt, (unsigned)c); }
            __syncthreads();
            if (tid == 0) {
                float t = 0.0f;
#pragma unroll
                for (int i = 0; i < NW; i++) t += w_f0[i];
                s_sum = t + (float)((int)K - (int)s_cnt) * thr;
            }
        }
        __syncthreads();
        hard = s_sum;
    }

    // ---- per-row results + last-CTA fused finalize ----
    if (tid == 0) {
        g_conf[b] = s_conf + hard;
        g_loc[b]  = s_loc;
        g_npos[b] = npos_b;
        __threadfence();
        unsigned v = atomicAdd(&g_ctr, 1u);
        s_last = (v == (unsigned)(BB - 1));
    }
    __syncthreads();

    if (s_last) {
        __threadfence();
        float l = 0.0f, c = 0.0f; int n = 0;
        if (tid < BB) { l = g_loc[tid]; c = g_conf[tid]; n = g_npos[tid]; }
#pragma unroll
        for (int o = 16; o; o >>= 1) {
            l += __shfl_down_sync(0xFFFFFFFFu, l, o);
            c += __shfl_down_sync(0xFFFFFFFFu, c, o);
        }
        n = __reduce_add_sync(0xFFFFFFFFu, n);
        if (lane == 0) { w_f0[warp] = l; w_f1[warp] = c; w_i0[warp] = n; }
        __syncthreads();
        if (tid == 0) {
            float locsum = 0.0f, confsum = 0.0f; long long np = 0;
#pragma unroll
            for (int i = 0; i < 4; i++) {   // rows live in warps 0-3 only
                locsum += w_f0[i]; confsum += w_f1[i]; np += w_i0[i];
            }
            float npf = (float)np;
            float loc_loss  = (np > 0) ? locsum / (4.0f * fmaxf(npf, 1.0f)) : 0.0f;
            float conf_loss = confsum / (1e-10f + npf);
            float total = conf_loss + loc_loss;
            if (out_size > 0) out[0] = total;
            if (out_size > 1) out[1] = conf_loss;
            if (out_size > 2) out[2] = loc_loss;
            g_ctr = 0u;    // reset for next graph replay
        }
        if (tid < BB && 3 + tid < out_size) out[3 + tid] = (float)g_npos[tid];
        for (int i = 3 + BB + tid; i < out_size; i += TPB) out[i] = 0.0f;
    }
}

extern "C" void kernel_launch(void* const* d_in, const int* in_sizes, int n_in,
                              void* d_out, int out_size) {
    const float* locs   = (const float*)d_in[0];   // (128,8732,4) f32
    const float* scores = (const float*)d_in[1];   // (128,8732,3) f32
    const float* boxes  = (const float*)d_in[2];   // (128,16,4)   f32
    const int*   labels = (const int*)d_in[3];     // (128,16)     i32
    const float* priors = (const float*)d_in[4];   // (8732,4)     f32

    multibox_kernel<<<BB, TPB>>>(locs, scores, boxes, labels, priors,
                                 (float*)d_out, out_size);
}

// round 12
// speedup vs baseline: 1.3099x; 1.3099x over previous
#include <cuda_runtime.h>
#include <cstdint>

#define BB 128
#define PP 8732
#define NG (PP/4)      // 2183
#define MM 16
#define TPB 512
#define NW (TPB/32)

__device__ float g_loc[BB];
__device__ float g_conf[BB];
__device__ int   g_npos[BB];
__device__ unsigned g_ctr = 0;

__device__ __forceinline__ unsigned midp(unsigned a, unsigned b) {
    return a + ((b - a + 1u) >> 1);   // candidate in [a+1, b] when b > a
}

__global__ __launch_bounds__(TPB, 1) void multibox_kernel(
    const float* __restrict__ locs,    // (B,P,4)
    const float* __restrict__ scores,  // (B,P,3)
    const float* __restrict__ boxes,   // (B,M,4) xyxy
    const int*   __restrict__ labels,  // (B,M)
    const float* __restrict__ priors,  // (P,4) cxcy
    float* __restrict__ out, int out_size)
{
    __shared__ __align__(16) float A[PP];            // sweep carry; later conf_neg
    __shared__ __align__(4)  unsigned char sobj[PP]; // obj | 0x80 positive flag
    __shared__ float4 sbox[MM];
    __shared__ float  sarea[MM];
    __shared__ float  bcx[MM], bcy[MM], bwd[MM], bht[MM];
    __shared__ int    blab[MM];
    __shared__ unsigned long long bestkey[MM];
    __shared__ float w_f0[NW], w_f1[NW], w_f2[NW];
    __shared__ int   w_i0[NW];
    __shared__ unsigned cnt[9];                      // 3 rotating sets x 3 counters
    __shared__ float s_conf, s_loc, s_sum, s_vmax;
    __shared__ int   s_np, s_last;
    __shared__ unsigned s_cnt;

    const int b    = blockIdx.x;
    const int tid  = threadIdx.x;
    const int warp = tid >> 5, lane = tid & 31;

    if (tid < MM) {
        float4 bb = *(const float4*)(boxes + ((size_t)b * MM + tid) * 4);
        sbox[tid] = bb;
        sarea[tid] = (bb.z - bb.x) * (bb.w - bb.y);
        bcx[tid] = (bb.x + bb.z) * 0.5f;
        bcy[tid] = (bb.y + bb.w) * 0.5f;
        bwd[tid] = bb.z - bb.x;
        bht[tid] = bb.w - bb.y;
        blab[tid] = labels[b * MM + tid];
        bestkey[tid] = 0ull;
    }
    if (tid < 9) cnt[tid] = 0u;
    __syncthreads();

    // ===== Phase 1: two sweeps of 8 objects each, boxes in REGISTERS,     =====
    // with software prefetch of the next prior (breaks load->use chain).
    // iou = inter/(S - inter), S = sarea[m] + parea.
    // iou1 > iou2  <=>  inter1*S2 > inter2*S1  (exact rational compare).
#pragma unroll 1
    for (int sweep = 0; sweep < 2; sweep++) {
        const int mbase = sweep * 8;
        float rx1[8], ry1[8], rx2[8], ry2[8], rsa[8];
#pragma unroll
        for (int m = 0; m < 8; m++) {
            float4 bb = sbox[mbase + m];
            rx1[m] = bb.x; ry1[m] = bb.y; rx2[m] = bb.z; ry2[m] = bb.w;
            rsa[m] = sarea[mbase + m];
        }
        float oi[8], oS[8]; int op[8];
#pragma unroll
        for (int m = 0; m < 8; m++) { oi[m] = 0.0f; oS[m] = 1.0f; op[m] = 0; }

        float4 pr = *(const float4*)(priors + (size_t)tid * 4);   // tid < PP always
        for (int p = tid; p < PP; p += TPB) {
            const int pn = p + TPB;
            float4 prn = *(const float4*)(priors + (size_t)(pn < PP ? pn : tid) * 4);

            float hw = pr.z * 0.5f, hh = pr.w * 0.5f;
            float px1 = pr.x - hw, py1 = pr.y - hh, px2 = pr.x + hw, py2 = pr.y + hh;
            float parea = pr.z * pr.w;

            float bint, bS; int bm;
            if (sweep == 0) { bint = 0.0f; bS = 1.0f; bm = 0; }
            else {
                bint = A[p];
                bm   = sobj[p];
                bS   = sarea[bm] + parea;   // bit-exact reconstruct
            }
#pragma unroll
            for (int m = 0; m < 8; m++) {
                float w = fminf(rx2[m], px2) - fmaxf(rx1[m], px1);
                float h = fminf(ry2[m], py2) - fmaxf(ry1[m], py1);
                float inter = fmaxf(w, 0.0f) * fmaxf(h, 0.0f);
                float S = rsa[m] + parea;
                if (inter * bS > bint * S) { bint = inter; bS = S; bm = mbase + m; }
                if (inter * oS[m] > oi[m] * S) { oi[m] = inter; oS[m] = S; op[m] = p; }
            }
            if (sweep == 0) {
                A[p] = bint;
                sobj[p] = (unsigned char)bm;
            } else {
                bool pos = (3.0f * bint >= bS);        // iou >= 0.5 exactly
                sobj[p] = (unsigned char)(bm | (pos ? 0x80 : 0));
            }
            pr = prn;
        }
#pragma unroll
        for (int m = 0; m < 8; m++) {
            float iou = __fdividef(oi[m], oS[m] - oi[m]);
            unsigned long long key =
                ((unsigned long long)__float_as_uint(iou) << 32) |
                (unsigned)(0xFFFFFFFFu - (unsigned)op[m]);
#pragma unroll
            for (int o = 16; o; o >>= 1) {
                unsigned long long other = __shfl_down_sync(0xFFFFFFFFu, key, o);
                if (other > key) key = other;
            }
            if (lane == 0) atomicMax(&bestkey[mbase + m], key);
        }
    }
    __syncthreads();

    // override: prior_obj[m] forced positive with object m (sequential, last wins)
    if (tid == 0) {
        for (int m = 0; m < MM; m++) {
            unsigned p = 0xFFFFFFFFu - (unsigned)(bestkey[m] & 0xFFFFFFFFull);
            sobj[p] = (unsigned char)(m | 0x80);
        }
    }
    __syncthreads();

    // ===== Phase 3: BCE + loc-loss, 2 groups/iter for MLP, conf_neg into A =====
    float conf_pos = 0.0f, loc_sum = 0.0f, vmax = 0.0f;
    int npos = 0;
    const float* srow = scores + (size_t)b * PP * 3;

    auto process_group = [&](int g, float4 s0, float4 s1, float4 s2, unsigned ob4) {
        float ch0[4] = { s0.x, s0.w, s1.z, s2.y };
        float ch1[4] = { s0.y, s1.x, s1.w, s2.z };
        float ch2[4] = { s0.z, s1.y, s2.x, s2.w };
        float v[4];
#pragma unroll
        for (int j = 0; j < 4; j++) {
            unsigned obf = (ob4 >> (8 * j)) & 0xFFu;
            int obj = (int)(obf & 0x7Fu);
            bool pos = (obf & 0x80u) != 0;
            float x0 = ch0[j], x1 = ch1[j], x2 = ch2[j];
            float bce = fmaxf(x0, 0.0f) + __logf(1.0f + __expf(-fabsf(x0)))
                      + fmaxf(x1, 0.0f) + __logf(1.0f + __expf(-fabsf(x1)))
                      + fmaxf(x2, 0.0f) + __logf(1.0f + __expf(-fabsf(x2)));
            int lab = pos ? blab[obj] : 0;
            if (lab == 0) bce -= x0;
            if (lab == 1 || lab == 3) bce -= x1;
            if (lab >= 2) bce -= x2;
            if (pos) {
                conf_pos += bce;
                npos++;
                v[j] = 0.0f;
                int p = 4 * g + j;
                float4 pr = *(const float4*)(priors + (size_t)p * 4);
                float gx = (bcx[obj] - pr.x) * 10.0f * __fdividef(1.0f, pr.z);
                float gy = (bcy[obj] - pr.y) * 10.0f * __fdividef(1.0f, pr.w);
                float gw = __logf(__fdividef(bwd[obj], pr.z)) * 5.0f;
                float gh = __logf(__fdividef(bht[obj], pr.w)) * 5.0f;
                float4 pl = *(const float4*)(locs + ((size_t)b * PP + p) * 4);
                loc_sum += fabsf(pl.x - gx) + fabsf(pl.y - gy) +
                           fabsf(pl.z - gw) + fabsf(pl.w - gh);
            } else {
                v[j] = bce;
            }
        }
        vmax = fmaxf(vmax, fmaxf(fmaxf(v[0], v[1]), fmaxf(v[2], v[3])));
        ((float4*)A)[g] = make_float4(v[0], v[1], v[2], v[3]);
    };

    for (int g0 = tid; g0 < NG; g0 += 2 * TPB) {
        const int g1 = g0 + TPB;
        const bool h2 = (g1 < NG);
        const int g1c = h2 ? g1 : g0;
        // issue all 6 independent loads up front (MLP = 6)
        const float4* sp0 = (const float4*)srow + (size_t)g0 * 3;
        const float4* sp1 = (const float4*)srow + (size_t)g1c * 3;
        float4 a0 = sp0[0], a1 = sp0[1], a2 = sp0[2];
        float4 c0 = sp1[0], c1 = sp1[1], c2 = sp1[2];
        unsigned obA = ((const unsigned*)sobj)[g0];
        unsigned obB = ((const unsigned*)sobj)[g1c];
        process_group(g0, a0, a1, a2, obA);
        if (h2) process_group(g1, c0, c1, c2, obB);
    }

    // ---- deterministic block reduce (sum conf/loc/npos, max vmax) ----
#pragma unroll
    for (int o = 16; o; o >>= 1) {
        conf_pos += __shfl_down_sync(0xFFFFFFFFu, conf_pos, o);
        loc_sum  += __shfl_down_sync(0xFFFFFFFFu, loc_sum, o);
        vmax      = fmaxf(vmax, __shfl_down_sync(0xFFFFFFFFu, vmax, o));
    }
    npos = __reduce_add_sync(0xFFFFFFFFu, npos);
    if (lane == 0) { w_f0[warp] = conf_pos; w_f1[warp] = loc_sum; w_f2[warp] = vmax; w_i0[warp] = npos; }
    __syncthreads();
    if (tid == 0) {
        float c = 0.0f, l = 0.0f, vm = 0.0f; int n = 0;
#pragma unroll
        for (int i = 0; i < NW; i++) {
            c += w_f0[i]; l += w_f1[i]; vm = fmaxf(vm, w_f2[i]); n += w_i0[i];
        }
        s_conf = c; s_loc = l; s_vmax = vm; s_np = n;
    }
    __syncthreads();

    const int npos_b = s_np;
    const unsigned K = 3u * (unsigned)npos_b;

    // ===== Phase 4: top-K sum, 4-way bisection with exact-count early exit =====
    // hi seeded with the true max of conf_neg (count(v >= max_bits) >= 1 and
    // the K-th largest is <= max, so the invariant holds).
    float hard = 0.0f;
    if (K > 0) {
        unsigned lo = 0u, hi = __float_as_uint(s_vmax);
        int r = 0;
        bool exact = false; unsigned tEx = 0u;
        const float4* sv4 = (const float4*)A;
        while (lo < hi) {
            unsigned c2v = midp(lo, hi);
            unsigned c1v = lo + ((c2v - lo) >> 1);
            unsigned c3v = midp(c2v, hi);
            int n1 = 0, n2 = 0, n3 = 0;
            for (int g = tid; g < NG; g += TPB) {
                float4 vv = sv4[g];
                unsigned u0 = __float_as_uint(vv.x), u1 = __float_as_uint(vv.y);
                unsigned u2 = __float_as_uint(vv.z), u3 = __float_as_uint(vv.w);
                n1 += (u0 >= c1v) + (u1 >= c1v) + (u2 >= c1v) + (u3 >= c1v);
                n2 += (u0 >= c2v) + (u1 >= c2v) + (u2 >= c2v) + (u3 >= c2v);
                n3 += (u0 >= c3v) + (u1 >= c3v) + (u2 >= c3v) + (u3 >= c3v);
            }
            n1 = __reduce_add_sync(0xFFFFFFFFu, n1);
            n2 = __reduce_add_sync(0xFFFFFFFFu, n2);
            n3 = __reduce_add_sync(0xFFFFFFFFu, n3);
            int s = (r % 3) * 3;
            if (lane == 0)      atomicAdd(&cnt[s + 0], (unsigned)n1);
            else if (lane == 1) atomicAdd(&cnt[s + 1], (unsigned)n2);
            else if (lane == 2) atomicAdd(&cnt[s + 2], (unsigned)n3);
            if (tid == 0) {
                int z = ((r + 1) % 3) * 3;
                cnt[z + 0] = 0u; cnt[z + 1] = 0u; cnt[z + 2] = 0u;
            }
            __syncthreads();
            unsigned N1 = cnt[s + 0], N2 = cnt[s + 1], N3 = cnt[s + 2];
            // exact hit: count(v >= t) == K  =>  topK sum = sum(v >= t)
            if (N2 == K)      { exact = true; tEx = c2v; }
            else if (N1 == K) { exact = true; tEx = c1v; }
            else if (N3 == K) { exact = true; tEx = c3v; }
            if (exact) break;           // uniform decision across the block
            if (N2 >= K) {
                lo = c2v;
                if (hi > lo) { if (N3 >= K) lo = c3v; else hi = c3v - 1u; }
            } else {
                hi = c2v - 1u;
                if (hi > lo) { if (N1 >= K) lo = c1v; else hi = c1v - 1u; }
            }
            r++;
        }
        if (tid == 0) s_cnt = 0u;
        __syncthreads();
        if (exact) {
            float ssum = 0.0f;
            for (int g = tid; g < NG; g += TPB) {
                float4 vv = sv4[g];
                if (__float_as_uint(vv.x) >= tEx) ssum += vv.x;
                if (__float_as_uint(vv.y) >= tEx) ssum += vv.y;
                if (__float_as_uint(vv.z) >= tEx) ssum += vv.z;
                if (__float_as_uint(vv.w) >= tEx) ssum += vv.w;
            }
#pragma unroll
            for (int o = 16; o; o >>= 1)
                ssum += __shfl_down_sync(0xFFFFFFFFu, ssum, o);
            if (lane == 0) w_f0[warp] = ssum;
            __syncthreads();
            if (tid == 0) {
                float t = 0.0f;
#pragma unroll
                for (int i = 0; i < NW; i++) t += w_f0[i];
                s_sum = t;
            }
        } else {
            const float thr = __uint_as_float(lo);
            int c = 0; float ssum = 0.0f;
            for (int g = tid; g < NG; g += TPB) {
                float4 vv = sv4[g];
                if (vv.x > thr) { c++; ssum += vv.x; }
                if (vv.y > thr) { c++; ssum += vv.y; }
                if (vv.z > thr) { c++; ssum += vv.z; }
                if (vv.w > thr) { c++; ssum += vv.w; }
            }
#pragma unroll
            for (int o = 16; o; o >>= 1)
                ssum += __shfl_down_sync(0xFFFFFFFFu, ssum, o);
            c = __reduce_add_sync(0xFFFFFFFFu, c);
            if (lane == 0) { w_f0[warp] = ssum; atomicAdd(&s_cnt, (unsigned)c); }
            __syncthreads();
            if (tid == 0) {
                float t = 0.0f;
#pragma unroll
                for (int i = 0; i < NW; i++) t += w_f0[i];
                s_sum = t + (float)((int)K - (int)s_cnt) * thr;
            }
        }
        __syncthreads();
        hard = s_sum;
    }

    // ---- per-row results + last-CTA fused finalize ----
    if (tid == 0) {
        g_conf[b] = s_conf + hard;
        g_loc[b]  = s_loc;
        g_npos[b] = npos_b;
        __threadfence();
        unsigned v = atomicAdd(&g_ctr, 1u);
        s_last = (v == (unsigned)(BB - 1));
    }
    __syncthreads();

    if (s_last) {
        __threadfence();
        float l = 0.0f, c = 0.0f; int n = 0;
        if (tid < BB) { l = g_loc[tid]; c = g_conf[tid]; n = g_npos[tid]; }
#pragma unroll
        for (int o = 16; o; o >>= 1) {
            l += __shfl_down_sync(0xFFFFFFFFu, l, o);
            c += __shfl_down_sync(0xFFFFFFFFu, c, o);
        }
        n = __reduce_add_sync(0xFFFFFFFFu, n);
        if (lane == 0) { w_f0[warp] = l; w_f1[warp] = c; w_i0[warp] = n; }
        __syncthreads();
        if (tid == 0) {
            float locsum = 0.0f, confsum = 0.0f; long long np = 0;
#pragma unroll
            for (int i = 0; i < 4; i++) {   // rows live in warps 0-3 only
                locsum += w_f0[i]; confsum += w_f1[i]; np += w_i0[i];
            }
            float npf = (float)np;
            float loc_loss  = (np > 0) ? locsum / (4.0f * fmaxf(npf, 1.0f)) : 0.0f;
            float conf_loss = confsum / (1e-10f + npf);
            float total = conf_loss + loc_loss;
            if (out_size > 0) out[0] = total;
            if (out_size > 1) out[1] = conf_loss;
            if (out_size > 2) out[2] = loc_loss;
            g_ctr = 0u;    // reset for next graph replay
        }
        if (tid < BB && 3 + tid < out_size) out[3 + tid] = (float)g_npos[tid];
        for (int i = 3 + BB + tid; i < out_size; i += TPB) out[i] = 0.0f;
    }
}

extern "C" void kernel_launch(void* const* d_in, const int* in_sizes, int n_in,
                              void* d_out, int out_size) {
    const float* locs   = (const float*)d_in[0];   // (128,8732,4) f32
    const float* scores = (const float*)d_in[1];   // (128,8732,3) f32
    const float* boxes  = (const float*)d_in[2];   // (128,16,4)   f32
    const int*   labels = (const int*)d_in[3];     // (128,16)     i32
    const float* priors = (const float*)d_in[4];   // (8732,4)     f32

    multibox_kernel<<<BB, TPB>>>(locs, scores, boxes, labels, priors,
                                 (float*)d_out, out_size);
}

// round 13
// speedup vs baseline: 1.3636x; 1.0410x over previous
#include <cuda_runtime.h>
#include <cstdint>

#define BB 128
#define PP 8732
#define NG (PP/4)      // 2183
#define MM 16
#define TPB 512
#define NW (TPB/32)

__device__ float g_loc[BB];
__device__ float g_conf[BB];
__device__ int   g_npos[BB];
__device__ unsigned g_ctr = 0;

__device__ __forceinline__ unsigned midp(unsigned a, unsigned b) {
    return a + ((b - a + 1u) >> 1);   // candidate in [a+1, b] when b > a
}

__global__ __launch_bounds__(TPB, 1) void multibox_kernel(
    const float* __restrict__ locs,    // (B,P,4)
    const float* __restrict__ scores,  // (B,P,3)
    const float* __restrict__ boxes,   // (B,M,4) xyxy
    const int*   __restrict__ labels,  // (B,M)
    const float* __restrict__ priors,  // (P,4) cxcy
    float* __restrict__ out, int out_size)
{
    __shared__ __align__(16) float A[PP];            // pos-list; later conf_neg
    __shared__ __align__(4)  unsigned char sobj[PP]; // 0 | 0x80|obj positive
    __shared__ float4 sbox[MM];
    __shared__ float  sarea[MM];
    __shared__ float  bcx[MM], bcy[MM], bwd[MM], bht[MM];
    __shared__ int    blab[MM];
    __shared__ unsigned long long bestkey[MM];
    __shared__ float w_f0[NW], w_f1[NW], w_f2[NW];
    __shared__ int   w_i0[NW];
    __shared__ unsigned cnt[9];                      // 3 rotating sets x 3 counters
    __shared__ float s_conf, s_loc, s_sum, s_vmax;
    __shared__ int   s_np, s_last, s_nlist;
    __shared__ unsigned s_cnt;

    const int b    = blockIdx.x;
    const int tid  = threadIdx.x;
    const int warp = tid >> 5, lane = tid & 31;

    if (tid < MM) {
        float4 bb = *(const float4*)(boxes + ((size_t)b * MM + tid) * 4);
        sbox[tid] = bb;
        sarea[tid] = (bb.z - bb.x) * (bb.w - bb.y);
        bcx[tid] = (bb.x + bb.z) * 0.5f;
        bcy[tid] = (bb.y + bb.w) * 0.5f;
        bwd[tid] = bb.z - bb.x;
        bht[tid] = bb.w - bb.y;
        blab[tid] = labels[b * MM + tid];
        bestkey[tid] = 0ull;
    }
    if (tid < 9) cnt[tid] = 0u;
    if (tid == 0) s_nlist = 0;
    __syncthreads();

    // ===== Phase 1: two sweeps of 8 objects, boxes in registers, prefetch. =====
    // Only computes: (a) pos = any_m(3*inter >= S)  (iou>=0.5 exactly)
    //                (b) per-object argmax over p (exact rational compare).
    // NO per-prior argmax here; done sparsely below for positives only.
    unsigned posmask = 0;               // bit i: prior tid + i*TPB is positive
#pragma unroll 1
    for (int sweep = 0; sweep < 2; sweep++) {
        const int mbase = sweep * 8;
        float rx1[8], ry1[8], rx2[8], ry2[8], rsa[8];
#pragma unroll
        for (int m = 0; m < 8; m++) {
            float4 bb = sbox[mbase + m];
            rx1[m] = bb.x; ry1[m] = bb.y; rx2[m] = bb.z; ry2[m] = bb.w;
            rsa[m] = sarea[mbase + m];
        }
        float oi[8], oS[8]; int op[8];
#pragma unroll
        for (int m = 0; m < 8; m++) { oi[m] = 0.0f; oS[m] = 1.0f; op[m] = 0; }

        float4 pr = *(const float4*)(priors + (size_t)tid * 4);   // tid < PP always
        int i = 0;
        for (int p = tid; p < PP; p += TPB, i++) {
            const int pn = p + TPB;
            float4 prn = *(const float4*)(priors + (size_t)(pn < PP ? pn : tid) * 4);

            float hw = pr.z * 0.5f, hh = pr.w * 0.5f;
            float px1 = pr.x - hw, py1 = pr.y - hh, px2 = pr.x + hw, py2 = pr.y + hh;
            float parea = pr.z * pr.w;
            bool pos = false;
#pragma unroll
            for (int m = 0; m < 8; m++) {
                float w = fminf(rx2[m], px2) - fmaxf(rx1[m], px1);
                float h = fminf(ry2[m], py2) - fmaxf(ry1[m], py1);
                float inter = fmaxf(w, 0.0f) * fmaxf(h, 0.0f);
                float S = rsa[m] + parea;
                pos |= (3.0f * inter >= S);            // iou >= 0.5 exactly
                if (inter * oS[m] > oi[m] * S) { oi[m] = inter; oS[m] = S; op[m] = p; }
            }
            if (pos) posmask |= (1u << i);
            pr = prn;
        }
        // cross-thread per-object argmax: key = (iou_bits, ~p)
#pragma unroll
        for (int m = 0; m < 8; m++) {
            float iou = __fdividef(oi[m], oS[m] - oi[m]);
            unsigned long long key =
                ((unsigned long long)__float_as_uint(iou) << 32) |
                (unsigned)(0xFFFFFFFFu - (unsigned)op[m]);
#pragma unroll
            for (int o = 16; o; o >>= 1) {
                unsigned long long other = __shfl_down_sync(0xFFFFFFFFu, key, o);
                if (other > key) key = other;
            }
            if (lane == 0) atomicMax(&bestkey[mbase + m], key);
        }
    }

    // flags + compact positive prior indices into A (order-free, work per entry
    // is independent & deterministic per p, so list order doesn't matter)
    {
        int i = 0;
        for (int p = tid; p < PP; p += TPB, i++) {
            bool pos = (posmask >> i) & 1u;
            sobj[p] = 0;
            if (pos) {
                int idx = atomicAdd(&s_nlist, 1);
                ((int*)A)[idx] = p;
            }
        }
    }
    __syncthreads();

    // sparse per-prior argmax: only for positives, dense across threads
    {
        const int nl = s_nlist;
        for (int i = tid; i < nl; i += TPB) {
            int p = ((int*)A)[i];
            float4 pr = *(const float4*)(priors + (size_t)p * 4);
            float hw = pr.z * 0.5f, hh = pr.w * 0.5f;
            float px1 = pr.x - hw, py1 = pr.y - hh, px2 = pr.x + hw, py2 = pr.y + hh;
            float parea = pr.z * pr.w;
            float bint = 0.0f, bS = 1.0f; int obj = 0;
#pragma unroll
            for (int m = 0; m < MM; m++) {
                float4 bb = sbox[m];
                float w = fminf(bb.z, px2) - fmaxf(bb.x, px1);
                float h = fminf(bb.w, py2) - fmaxf(bb.y, py1);
                float inter = fmaxf(w, 0.0f) * fmaxf(h, 0.0f);
                float S = sarea[m] + parea;
                if (inter * bS > bint * S) { bint = inter; bS = S; obj = m; }
            }
            sobj[p] = (unsigned char)(0x80 | obj);
        }
    }
    __syncthreads();

    // override: prior_obj[m] forced positive with object m (sequential, last wins)
    if (tid == 0) {
        for (int m = 0; m < MM; m++) {
            unsigned p = 0xFFFFFFFFu - (unsigned)(bestkey[m] & 0xFFFFFFFFull);
            sobj[p] = (unsigned char)(0x80 | m);
        }
    }
    __syncthreads();

    // ===== Phase 3: BCE + loc-loss, 2 groups/iter for MLP, conf_neg into A =====
    float conf_pos = 0.0f, loc_sum = 0.0f, vmax = 0.0f;
    int npos = 0;
    const float* srow = scores + (size_t)b * PP * 3;

    auto process_group = [&](int g, float4 s0, float4 s1, float4 s2, unsigned ob4) {
        float ch0[4] = { s0.x, s0.w, s1.z, s2.y };
        float ch1[4] = { s0.y, s1.x, s1.w, s2.z };
        float ch2[4] = { s0.z, s1.y, s2.x, s2.w };
        float v[4];
#pragma unroll
        for (int j = 0; j < 4; j++) {
            unsigned obf = (ob4 >> (8 * j)) & 0xFFu;
            int obj = (int)(obf & 0x7Fu);
            bool pos = (obf & 0x80u) != 0;
            float x0 = ch0[j], x1 = ch1[j], x2 = ch2[j];
            float bce = fmaxf(x0, 0.0f) + __logf(1.0f + __expf(-fabsf(x0)))
                      + fmaxf(x1, 0.0f) + __logf(1.0f + __expf(-fabsf(x1)))
                      + fmaxf(x2, 0.0f) + __logf(1.0f + __expf(-fabsf(x2)));
            int lab = pos ? blab[obj] : 0;
            if (lab == 0) bce -= x0;
            if (lab == 1 || lab == 3) bce -= x1;
            if (lab >= 2) bce -= x2;
            if (pos) {
                conf_pos += bce;
                npos++;
                v[j] = 0.0f;
                int p = 4 * g + j;
                float4 pr = *(const float4*)(priors + (size_t)p * 4);
                float gx = (bcx[obj] - pr.x) * 10.0f * __fdividef(1.0f, pr.z);
                float gy = (bcy[obj] - pr.y) * 10.0f * __fdividef(1.0f, pr.w);
                float gw = __logf(__fdividef(bwd[obj], pr.z)) * 5.0f;
                float gh = __logf(__fdividef(bht[obj], pr.w)) * 5.0f;
                float4 pl = *(const float4*)(locs + ((size_t)b * PP + p) * 4);
                loc_sum += fabsf(pl.x - gx) + fabsf(pl.y - gy) +
                           fabsf(pl.z - gw) + fabsf(pl.w - gh);
            } else {
                v[j] = bce;
            }
        }
        vmax = fmaxf(vmax, fmaxf(fmaxf(v[0], v[1]), fmaxf(v[2], v[3])));
        ((float4*)A)[g] = make_float4(v[0], v[1], v[2], v[3]);
    };

    for (int g0 = tid; g0 < NG; g0 += 2 * TPB) {
        const int g1 = g0 + TPB;
        const bool h2 = (g1 < NG);
        const int g1c = h2 ? g1 : g0;
        const float4* sp0 = (const float4*)srow + (size_t)g0 * 3;
        const float4* sp1 = (const float4*)srow + (size_t)g1c * 3;
        float4 a0 = sp0[0], a1 = sp0[1], a2 = sp0[2];
        float4 c0 = sp1[0], c1 = sp1[1], c2 = sp1[2];
        unsigned obA = ((const unsigned*)sobj)[g0];
        unsigned obB = ((const unsigned*)sobj)[g1c];
        process_group(g0, a0, a1, a2, obA);
        if (h2) process_group(g1, c0, c1, c2, obB);
    }

    // ---- deterministic block reduce (sum conf/loc/npos, max vmax) ----
#pragma unroll
    for (int o = 16; o; o >>= 1) {
        conf_pos += __shfl_down_sync(0xFFFFFFFFu, conf_pos, o);
        loc_sum  += __shfl_down_sync(0xFFFFFFFFu, loc_sum, o);
        vmax      = fmaxf(vmax, __shfl_down_sync(0xFFFFFFFFu, vmax, o));
    }
    npos = __reduce_add_sync(0xFFFFFFFFu, npos);
    if (lane == 0) { w_f0[warp] = conf_pos; w_f1[warp] = loc_sum; w_f2[warp] = vmax; w_i0[warp] = npos; }
    __syncthreads();
    if (tid == 0) {
        float c = 0.0f, l = 0.0f, vm = 0.0f; int n = 0;
#pragma unroll
        for (int i = 0; i < NW; i++) {
            c += w_f0[i]; l += w_f1[i]; vm = fmaxf(vm, w_f2[i]); n += w_i0[i];
        }
        s_conf = c; s_loc = l; s_vmax = vm; s_np = n;
    }
    __syncthreads();

    const int npos_b = s_np;
    const unsigned K = 3u * (unsigned)npos_b;

    // ===== Phase 4: top-K sum, 4-way bisection, vmax-seeded, early exit =====
    float hard = 0.0f;
    if (K > 0) {
        unsigned lo = 0u, hi = __float_as_uint(s_vmax);
        int r = 0;
        bool exact = false; unsigned tEx = 0u;
        const float4* sv4 = (const float4*)A;
        while (lo < hi) {
            unsigned c2v = midp(lo, hi);
            unsigned c1v = lo + ((c2v - lo) >> 1);
            unsigned c3v = midp(c2v, hi);
            int n1 = 0, n2 = 0, n3 = 0;
            for (int g = tid; g < NG; g += TPB) {
                float4 vv = sv4[g];
                unsigned u0 = __float_as_uint(vv.x), u1 = __float_as_uint(vv.y);
                unsigned u2 = __float_as_uint(vv.z), u3 = __float_as_uint(vv.w);
                n1 += (u0 >= c1v) + (u1 >= c1v) + (u2 >= c1v) + (u3 >= c1v);
                n2 += (u0 >= c2v) + (u1 >= c2v) + (u2 >= c2v) + (u3 >= c2v);
                n3 += (u0 >= c3v) + (u1 >= c3v) + (u2 >= c3v) + (u3 >= c3v);
            }
            n1 = __reduce_add_sync(0xFFFFFFFFu, n1);
            n2 = __reduce_add_sync(0xFFFFFFFFu, n2);
            n3 = __reduce_add_sync(0xFFFFFFFFu, n3);
            int s = (r % 3) * 3;
            if (lane == 0)      atomicAdd(&cnt[s + 0], (unsigned)n1);
            else if (lane == 1) atomicAdd(&cnt[s + 1], (unsigned)n2);
            else if (lane == 2) atomicAdd(&cnt[s + 2], (unsigned)n3);
            if (tid == 0) {
                int z = ((r + 1) % 3) * 3;
                cnt[z + 0] = 0u; cnt[z + 1] = 0u; cnt[z + 2] = 0u;
            }
            __syncthreads();
            unsigned N1 = cnt[s + 0], N2 = cnt[s + 1], N3 = cnt[s + 2];
            if (N2 == K)      { exact = true; tEx = c2v; }
            else if (N1 == K) { exact = true; tEx = c1v; }
            else if (N3 == K) { exact = true; tEx = c3v; }
            if (exact) break;           // uniform decision across the block
            if (N2 >= K) {
                lo = c2v;
                if (hi > lo) { if (N3 >= K) lo = c3v; else hi = c3v - 1u; }
            } else {
                hi = c2v - 1u;
                if (hi > lo) { if (N1 >= K) lo = c1v; else hi = c1v - 1u; }
            }
            r++;
        }
        if (tid == 0) s_cnt = 0u;
        __syncthreads();
        if (exact) {
            float ssum = 0.0f;
            for (int g = tid; g < NG; g += TPB) {
                float4 vv = sv4[g];
                if (__float_as_uint(vv.x) >= tEx) ssum += vv.x;
                if (__float_as_uint(vv.y) >= tEx) ssum += vv.y;
                if (__float_as_uint(vv.z) >= tEx) ssum += vv.z;
                if (__float_as_uint(vv.w) >= tEx) ssum += vv.w;
            }
#pragma unroll
            for (int o = 16; o; o >>= 1)
                ssum += __shfl_down_sync(0xFFFFFFFFu, ssum, o);
            if (lane == 0) w_f0[warp] = ssum;
            __syncthreads();
            if (tid == 0) {
                float t = 0.0f;
#pragma unroll
                for (int i = 0; i < NW; i++) t += w_f0[i];
                s_sum = t;
            }
        } else {
            const float thr = __uint_as_float(lo);
            int c = 0; float ssum = 0.0f;
            for (int g = tid; g < NG; g += TPB) {
                float4 vv = sv4[g];
                if (vv.x > thr) { c++; ssum += vv.x; }
                if (vv.y > thr) { c++; ssum += vv.y; }
                if (vv.z > thr) { c++; ssum += vv.z; }
                if (vv.w > thr) { c++; ssum += vv.w; }
            }
#pragma unroll
            for (int o = 16; o; o >>= 1)
                ssum += __shfl_down_sync(0xFFFFFFFFu, ssum, o);
            c = __reduce_add_sync(0xFFFFFFFFu, c);
            if (lane == 0) { w_f0[warp] = ssum; atomicAdd(&s_cnt, (unsigned)c); }
            __syncthreads();
            if (tid == 0) {
                float t = 0.0f;
#pragma unroll
                for (int i = 0; i < NW; i++) t += w_f0[i];
                s_sum = t + (float)((int)K - (int)s_cnt) * thr;
            }
        }
        __syncthreads();
        hard = s_sum;
    }

    // ---- per-row results + last-CTA fused finalize ----
    if (tid == 0) {
        g_conf[b] = s_conf + hard;
        g_loc[b]  = s_loc;
        g_npos[b] = npos_b;
        __threadfence();
        unsigned v = atomicAdd(&g_ctr, 1u);
        s_last = (v == (unsigned)(BB - 1));
    }
    __syncthreads();

    if (s_last) {
        __threadfence();
        float l = 0.0f, c = 0.0f; int n = 0;
        if (tid < BB) { l = g_loc[tid]; c = g_conf[tid]; n = g_npos[tid]; }
#pragma unroll
        for (int o = 16; o; o >>= 1) {
            l += __shfl_down_sync(0xFFFFFFFFu, l, o);
            c += __shfl_down_sync(0xFFFFFFFFu, c, o);
        }
        n = __reduce_add_sync(0xFFFFFFFFu, n);
        if (lane == 0) { w_f0[warp] = l; w_f1[warp] = c; w_i0[warp] = n; }
        __syncthreads();
        if (tid == 0) {
            float locsum = 0.0f, confsum = 0.0f; long long np = 0;
#pragma unroll
            for (int i = 0; i < 4; i++) {   // rows live in warps 0-3 only
                locsum += w_f0[i]; confsum += w_f1[i]; np += w_i0[i];
            }
            float npf = (float)np;
            float loc_loss  = (np > 0) ? locsum / (4.0f * fmaxf(npf, 1.0f)) : 0.0f;
            float conf_loss = confsum / (1e-10f + npf);
            float total = conf_loss + loc_loss;
            if (out_size > 0) out[0] = total;
            if (out_size > 1) out[1] = conf_loss;
            if (out_size > 2) out[2] = loc_loss;
            g_ctr = 0u;    // reset for next graph replay
        }
        if (tid < BB && 3 + tid < out_size) out[3 + tid] = (float)g_npos[tid];
        for (int i = 3 + BB + tid; i < out_size; i += TPB) out[i] = 0.0f;
    }
}

extern "C" void kernel_launch(void* const* d_in, const int* in_sizes, int n_in,
                              void* d_out, int out_size) {
    const float* locs   = (const float*)d_in[0];   // (128,8732,4) f32
    const float* scores = (const float*)d_in[1];   // (128,8732,3) f32
    const float* boxes  = (const float*)d_in[2];   // (128,16,4)   f32
    const int*   labels = (const int*)d_in[3];     // (128,16)     i32
    const float* priors = (const float*)d_in[4];   // (8732,4)     f32

    multibox_kernel<<<BB, TPB>>>(locs, scores, boxes, labels, priors,
                                 (float*)d_out, out_size);
}

// round 14
// speedup vs baseline: 1.3716x; 1.0059x over previous
#include <cuda_runtime.h>
#include <cstdint>

#define BB 128
#define PP 8732
#define NG (PP/4)      // 2183
#define MM 16
#define TPB 512
#define NW (TPB/32)

__device__ float g_loc[BB];
__device__ float g_conf[BB];
__device__ int   g_npos[BB];
__device__ unsigned g_ctr = 0;

__device__ __forceinline__ unsigned midp(unsigned a, unsigned b) {
    return a + ((b - a + 1u) >> 1);   // candidate in [a+1, b] when b > a
}

__global__ __launch_bounds__(TPB, 1) void multibox_kernel(
    const float* __restrict__ locs,    // (B,P,4)
    const float* __restrict__ scores,  // (B,P,3)
    const float* __restrict__ boxes,   // (B,M,4) xyxy
    const int*   __restrict__ labels,  // (B,M)
    const float* __restrict__ priors,  // (P,4) cxcy
    float* __restrict__ out, int out_size)
{
    __shared__ __align__(16) float A[PP];            // pos-list; later conf_neg
    __shared__ __align__(4)  unsigned char sobj[PP]; // 0 | 0x80|obj positive
    __shared__ float4 sbox[MM];
    __shared__ float  sarea[MM];
    __shared__ float  bcx[MM], bcy[MM], bwd[MM], bht[MM];
    __shared__ int    blab[MM];
    __shared__ unsigned long long bestkey[MM];
    __shared__ float w_f0[NW], w_f1[NW], w_f2[NW];
    __shared__ int   w_i0[NW];
    __shared__ unsigned cnt[9];                      // 3 rotating sets x 3 counters
    __shared__ float s_conf, s_loc, s_sum, s_vmax;
    __shared__ int   s_np, s_last, s_nlist;
    __shared__ unsigned s_cnt;

    const int b    = blockIdx.x;
    const int tid  = threadIdx.x;
    const int warp = tid >> 5, lane = tid & 31;

    if (tid < MM) {
        float4 bb = *(const float4*)(boxes + ((size_t)b * MM + tid) * 4);
        sbox[tid] = bb;
        sarea[tid] = (bb.z - bb.x) * (bb.w - bb.y);
        bcx[tid] = (bb.x + bb.z) * 0.5f;
        bcy[tid] = (bb.y + bb.w) * 0.5f;
        bwd[tid] = bb.z - bb.x;
        bht[tid] = bb.w - bb.y;
        blab[tid] = labels[b * MM + tid];
        bestkey[tid] = 0ull;
    }
    if (tid < 9) cnt[tid] = 0u;
    if (tid == 0) s_nlist = 0;
    __syncthreads();

    // ===== Phase 1: two sweeps of 8 objects, boxes in registers,          =====
    // 2 priors per iteration (independent chains) with pair prefetch.
    // Only computes: pos = any_m(3*inter >= S)  and per-object argmax over p.
    // Merged tracker update: winner-of-pair first (strict >, smaller p wins
    // ties), then tracker compare — identical semantics to sequential scan.
    unsigned posmask = 0;               // bit k: prior tid + k*TPB is positive
#pragma unroll 1
    for (int sweep = 0; sweep < 2; sweep++) {
        const int mbase = sweep * 8;
        float rx1[8], ry1[8], rx2[8], ry2[8], rsa[8];
#pragma unroll
        for (int m = 0; m < 8; m++) {
            float4 bb = sbox[mbase + m];
            rx1[m] = bb.x; ry1[m] = bb.y; rx2[m] = bb.z; ry2[m] = bb.w;
            rsa[m] = sarea[mbase + m];
        }
        float oi[8], oS[8]; int op[8];
#pragma unroll
        for (int m = 0; m < 8; m++) { oi[m] = 0.0f; oS[m] = 1.0f; op[m] = 0; }

        // pipelined pair loop: (tid + 2k*TPB, tid + (2k+1)*TPB)
        float4 pr0 = *(const float4*)(priors + (size_t)tid * 4);
        float4 pr1 = *(const float4*)(priors + (size_t)(tid + TPB) * 4); // < PP
        int i = 0;
        int p = tid;
        for (; p + TPB < PP; p += 2 * TPB, i += 2) {
            const int pn0 = p + 2 * TPB, pn1 = p + 3 * TPB;
            float4 nx0 = *(const float4*)(priors + (size_t)(pn0 < PP ? pn0 : tid) * 4);
            float4 nx1 = *(const float4*)(priors + (size_t)(pn1 < PP ? pn1 : tid) * 4);

            float ahw = pr0.z * 0.5f, ahh = pr0.w * 0.5f;
            float ax1 = pr0.x - ahw, ay1 = pr0.y - ahh;
            float ax2 = pr0.x + ahw, ay2 = pr0.y + ahh;
            float aarea = pr0.z * pr0.w;
            float bhw = pr1.z * 0.5f, bhh = pr1.w * 0.5f;
            float bx1 = pr1.x - bhw, by1 = pr1.y - bhh;
            float bx2 = pr1.x + bhw, by2 = pr1.y + bhh;
            float barea = pr1.z * pr1.w;
            bool pos0 = false, pos1 = false;
#pragma unroll
            for (int m = 0; m < 8; m++) {
                // prior A
                float wA = fminf(rx2[m], ax2) - fmaxf(rx1[m], ax1);
                float hA = fminf(ry2[m], ay2) - fmaxf(ry1[m], ay1);
                float iA = fmaxf(wA, 0.0f) * fmaxf(hA, 0.0f);
                float SA = rsa[m] + aarea;
                // prior B (independent chain)
                float wB = fminf(rx2[m], bx2) - fmaxf(rx1[m], bx1);
                float hB = fminf(ry2[m], by2) - fmaxf(ry1[m], by1);
                float iB = fmaxf(wB, 0.0f) * fmaxf(hB, 0.0f);
                float SB = rsa[m] + barea;
                pos0 |= (3.0f * iA >= SA);
                pos1 |= (3.0f * iB >= SB);
                // winner of the pair (strict >: smaller p wins ties)
                bool w2 = (iB * SA > iA * SB);
                float wi = w2 ? iB : iA;
                float wS = w2 ? SB : SA;
                int   wp = w2 ? p + TPB : p;
                if (wi * oS[m] > oi[m] * wS) { oi[m] = wi; oS[m] = wS; op[m] = wp; }
            }
            if (pos0) posmask |= (1u << i);
            if (pos1) posmask |= (2u << i);
            pr0 = nx0; pr1 = nx1;
        }
        if (p < PP) {   // tail: single prior (pr0)
            float ahw = pr0.z * 0.5f, ahh = pr0.w * 0.5f;
            float ax1 = pr0.x - ahw, ay1 = pr0.y - ahh;
            float ax2 = pr0.x + ahw, ay2 = pr0.y + ahh;
            float aarea = pr0.z * pr0.w;
            bool pos0 = false;
#pragma unroll
            for (int m = 0; m < 8; m++) {
                float wA = fminf(rx2[m], ax2) - fmaxf(rx1[m], ax1);
                float hA = fminf(ry2[m], ay2) - fmaxf(ry1[m], ay1);
                float iA = fmaxf(wA, 0.0f) * fmaxf(hA, 0.0f);
                float SA = rsa[m] + aarea;
                pos0 |= (3.0f * iA >= SA);
                if (iA * oS[m] > oi[m] * SA) { oi[m] = iA; oS[m] = SA; op[m] = p; }
            }
            if (pos0) posmask |= (1u << i);
        }
        // cross-thread per-object argmax: key = (iou_bits, ~p)
#pragma unroll
        for (int m = 0; m < 8; m++) {
            float iou = __fdividef(oi[m], oS[m] - oi[m]);
            unsigned long long key =
                ((unsigned long long)__float_as_uint(iou) << 32) |
                (unsigned)(0xFFFFFFFFu - (unsigned)op[m]);
#pragma unroll
            for (int o = 16; o; o >>= 1) {
                unsigned long long other = __shfl_down_sync(0xFFFFFFFFu, key, o);
                if (other > key) key = other;
            }
            if (lane == 0) atomicMax(&bestkey[mbase + m], key);
        }
    }

    // flags + compact positive prior indices into A (order-free; per-entry
    // work is independent & deterministic per p, so list order doesn't matter)
    {
        int i = 0;
        for (int p = tid; p < PP; p += TPB, i++) {
            bool pos = (posmask >> i) & 1u;
            sobj[p] = 0;
            if (pos) {
                int idx = atomicAdd(&s_nlist, 1);
                ((int*)A)[idx] = p;
            }
        }
    }
    __syncthreads();

    // sparse per-prior argmax: only for positives, dense across threads
    {
        const int nl = s_nlist;
        for (int i = tid; i < nl; i += TPB) {
            int p = ((int*)A)[i];
            float4 pr = *(const float4*)(priors + (size_t)p * 4);
            float hw = pr.z * 0.5f, hh = pr.w * 0.5f;
            float px1 = pr.x - hw, py1 = pr.y - hh, px2 = pr.x + hw, py2 = pr.y + hh;
            float parea = pr.z * pr.w;
            float bint = 0.0f, bS = 1.0f; int obj = 0;
#pragma unroll
            for (int m = 0; m < MM; m++) {
                float4 bb = sbox[m];
                float w = fminf(bb.z, px2) - fmaxf(bb.x, px1);
                float h = fminf(bb.w, py2) - fmaxf(bb.y, py1);
                float inter = fmaxf(w, 0.0f) * fmaxf(h, 0.0f);
                float S = sarea[m] + parea;
                if (inter * bS > bint * S) { bint = inter; bS = S; obj = m; }
            }
            sobj[p] = (unsigned char)(0x80 | obj);
        }
    }
    __syncthreads();

    // override: prior_obj[m] forced positive with object m (sequential, last wins)
    if (tid == 0) {
        for (int m = 0; m < MM; m++) {
            unsigned p = 0xFFFFFFFFu - (unsigned)(bestkey[m] & 0xFFFFFFFFull);
            sobj[p] = (unsigned char)(0x80 | m);
        }
    }
    __syncthreads();

    // ===== Phase 3: BCE + loc-loss, 2 groups/iter for MLP, conf_neg into A =====
    float conf_pos = 0.0f, loc_sum = 0.0f, vmax = 0.0f;
    int npos = 0;
    const float* srow = scores + (size_t)b * PP * 3;

    auto process_group = [&](int g, float4 s0, float4 s1, float4 s2, unsigned ob4) {
        float ch0[4] = { s0.x, s0.w, s1.z, s2.y };
        float ch1[4] = { s0.y, s1.x, s1.w, s2.z };
        float ch2[4] = { s0.z, s1.y, s2.x, s2.w };
        float v[4];
#pragma unroll
        for (int j = 0; j < 4; j++) {
            unsigned obf = (ob4 >> (8 * j)) & 0xFFu;
            int obj = (int)(obf & 0x7Fu);
            bool pos = (obf & 0x80u) != 0;
            float x0 = ch0[j], x1 = ch1[j], x2 = ch2[j];
            float bce = fmaxf(x0, 0.0f) + __logf(1.0f + __expf(-fabsf(x0)))
                      + fmaxf(x1, 0.0f) + __logf(1.0f + __expf(-fabsf(x1)))
                      + fmaxf(x2, 0.0f) + __logf(1.0f + __expf(-fabsf(x2)));
            int lab = pos ? blab[obj] : 0;
            if (lab == 0) bce -= x0;
            if (lab == 1 || lab == 3) bce -= x1;
            if (lab >= 2) bce -= x2;
            if (pos) {
                conf_pos += bce;
                npos++;
                v[j] = 0.0f;
                int p = 4 * g + j;
                float4 pr = *(const float4*)(priors + (size_t)p * 4);
                float gx = (bcx[obj] - pr.x) * 10.0f * __fdividef(1.0f, pr.z);
                float gy = (bcy[obj] - pr.y) * 10.0f * __fdividef(1.0f, pr.w);
                float gw = __logf(__fdividef(bwd[obj], pr.z)) * 5.0f;
                float gh = __logf(__fdividef(bht[obj], pr.w)) * 5.0f;
                float4 pl = *(const float4*)(locs + ((size_t)b * PP + p) * 4);
                loc_sum += fabsf(pl.x - gx) + fabsf(pl.y - gy) +
                           fabsf(pl.z - gw) + fabsf(pl.w - gh);
            } else {
                v[j] = bce;
            }
        }
        vmax = fmaxf(vmax, fmaxf(fmaxf(v[0], v[1]), fmaxf(v[2], v[3])));
        ((float4*)A)[g] = make_float4(v[0], v[1], v[2], v[3]);
    };

    for (int g0 = tid; g0 < NG; g0 += 2 * TPB) {
        const int g1 = g0 + TPB;
        const bool h2 = (g1 < NG);
        const int g1c = h2 ? g1 : g0;
        const float4* sp0 = (const float4*)srow + (size_t)g0 * 3;
        const float4* sp1 = (const float4*)srow + (size_t)g1c * 3;
        float4 a0 = sp0[0], a1 = sp0[1], a2 = sp0[2];
        float4 c0 = sp1[0], c1 = sp1[1], c2 = sp1[2];
        unsigned obA = ((const unsigned*)sobj)[g0];
        unsigned obB = ((const unsigned*)sobj)[g1c];
        process_group(g0, a0, a1, a2, obA);
        if (h2) process_group(g1, c0, c1, c2, obB);
    }

    // ---- deterministic block reduce (sum conf/loc/npos, max vmax) ----
#pragma unroll
    for (int o = 16; o; o >>= 1) {
        conf_pos += __shfl_down_sync(0xFFFFFFFFu, conf_pos, o);
        loc_sum  += __shfl_down_sync(0xFFFFFFFFu, loc_sum, o);
        vmax      = fmaxf(vmax, __shfl_down_sync(0xFFFFFFFFu, vmax, o));
    }
    npos = __reduce_add_sync(0xFFFFFFFFu, npos);
    if (lane == 0) { w_f0[warp] = conf_pos; w_f1[warp] = loc_sum; w_f2[warp] = vmax; w_i0[warp] = npos; }
    __syncthreads();
    if (tid == 0) {
        float c = 0.0f, l = 0.0f, vm = 0.0f; int n = 0;
#pragma unroll
        for (int i = 0; i < NW; i++) {
            c += w_f0[i]; l += w_f1[i]; vm = fmaxf(vm, w_f2[i]); n += w_i0[i];
        }
        s_conf = c; s_loc = l; s_vmax = vm; s_np = n;
    }
    __syncthreads();

    const int npos_b = s_np;
    const unsigned K = 3u * (unsigned)npos_b;

    // ===== Phase 4: top-K sum, 4-way bisection, vmax-seeded, early exit =====
    float hard = 0.0f;
    if (K > 0) {
        unsigned lo = 0u, hi = __float_as_uint(s_vmax);
        int r = 0;
        bool exact = false; unsigned tEx = 0u;
        const float4* sv4 = (const float4*)A;
        while (lo < hi) {
            unsigned c2v = midp(lo, hi);
            unsigned c1v = lo + ((c2v - lo) >> 1);
            unsigned c3v = midp(c2v, hi);
            int n1 = 0, n2 = 0, n3 = 0;
            for (int g = tid; g < NG; g += TPB) {
                float4 vv = sv4[g];
                unsigned u0 = __float_as_uint(vv.x), u1 = __float_as_uint(vv.y);
                unsigned u2 = __float_as_uint(vv.z), u3 = __float_as_uint(vv.w);
                n1 += (u0 >= c1v) + (u1 >= c1v) + (u2 >= c1v) + (u3 >= c1v);
                n2 += (u0 >= c2v) + (u1 >= c2v) + (u2 >= c2v) + (u3 >= c2v);
                n3 += (u0 >= c3v) + (u1 >= c3v) + (u2 >= c3v) + (u3 >= c3v);
            }
            n1 = __reduce_add_sync(0xFFFFFFFFu, n1);
            n2 = __reduce_add_sync(0xFFFFFFFFu, n2);
            n3 = __reduce_add_sync(0xFFFFFFFFu, n3);
            int s = (r % 3) * 3;
            if (lane == 0)      atomicAdd(&cnt[s + 0], (unsigned)n1);
            else if (lane == 1) atomicAdd(&cnt[s + 1], (unsigned)n2);
            else if (lane == 2) atomicAdd(&cnt[s + 2], (unsigned)n3);
            if (tid == 0) {
                int z = ((r + 1) % 3) * 3;
                cnt[z + 0] = 0u; cnt[z + 1] = 0u; cnt[z + 2] = 0u;
            }
            __syncthreads();
            unsigned N1 = cnt[s + 0], N2 = cnt[s + 1], N3 = cnt[s + 2];
            if (N2 == K)      { exact = true; tEx = c2v; }
            else if (N1 == K) { exact = true; tEx = c1v; }
            else if (N3 == K) { exact = true; tEx = c3v; }
            if (exact) break;           // uniform decision across the block
            if (N2 >= K) {
                lo = c2v;
                if (hi > lo) { if (N3 >= K) lo = c3v; else hi = c3v - 1u; }
            } else {
                hi = c2v - 1u;
                if (hi > lo) { if (N1 >= K) lo = c1v; else hi = c1v - 1u; }
            }
            r++;
        }
        if (tid == 0) s_cnt = 0u;
        __syncthreads();
        if (exact) {
            float ssum = 0.0f;
            for (int g = tid; g < NG; g += TPB) {
                float4 vv = sv4[g];
                if (__float_as_uint(vv.x) >= tEx) ssum += vv.x;
                if (__float_as_uint(vv.y) >= tEx) ssum += vv.y;
                if (__float_as_uint(vv.z) >= tEx) ssum += vv.z;
                if (__float_as_uint(vv.w) >= tEx) ssum += vv.w;
            }
#pragma unroll
            for (int o = 16; o; o >>= 1)
                ssum += __shfl_down_sync(0xFFFFFFFFu, ssum, o);
            if (lane == 0) w_f0[warp] = ssum;
            __syncthreads();
            if (tid == 0) {
                float t = 0.0f;
#pragma unroll
                for (int i = 0; i < NW; i++) t += w_f0[i];
                s_sum = t;
            }
        } else {
            const float thr = __uint_as_float(lo);
            int c = 0; float ssum = 0.0f;
            for (int g = tid; g < NG; g += TPB) {
                float4 vv = sv4[g];
                if (vv.x > thr) { c++; ssum += vv.x; }
                if (vv.y > thr) { c++; ssum += vv.y; }
                if (vv.z > thr) { c++; ssum += vv.z; }
                if (vv.w > thr) { c++; ssum += vv.w; }
            }
#pragma unroll
            for (int o = 16; o; o >>= 1)
                ssum += __shfl_down_sync(0xFFFFFFFFu, ssum, o);
            c = __reduce_add_sync(0xFFFFFFFFu, c);
            if (lane == 0) { w_f0[warp] = ssum; atomicAdd(&s_cnt, (unsigned)c); }
            __syncthreads();
            if (tid == 0) {
                float t = 0.0f;
#pragma unroll
                for (int i = 0; i < NW; i++) t += w_f0[i];
                s_sum = t + (float)((int)K - (int)s_cnt) * thr;
            }
        }
        __syncthreads();
        hard = s_sum;
    }

    // ---- per-row results + last-CTA fused finalize ----
    if (tid == 0) {
        g_conf[b] = s_conf + hard;
        g_loc[b]  = s_loc;
        g_npos[b] = npos_b;
        __threadfence();
        unsigned v = atomicAdd(&g_ctr, 1u);
        s_last = (v == (unsigned)(BB - 1));
    }
    __syncthreads();

    if (s_last) {
        __threadfence();
        float l = 0.0f, c = 0.0f; int n = 0;
        if (tid < BB) { l = g_loc[tid]; c = g_conf[tid]; n = g_npos[tid]; }
#pragma unroll
        for (int o = 16; o; o >>= 1) {
            l += __shfl_down_sync(0xFFFFFFFFu, l, o);
            c += __shfl_down_sync(0xFFFFFFFFu, c, o);
        }
        n = __reduce_add_sync(0xFFFFFFFFu, n);
        if (lane == 0) { w_f0[warp] = l; w_f1[warp] = c; w_i0[warp] = n; }
        __syncthreads();
        if (tid == 0) {
            float locsum = 0.0f, confsum = 0.0f; long long np = 0;
#pragma unroll
            for (int i = 0; i < 4; i++) {   // rows live in warps 0-3 only
                locsum += w_f0[i]; confsum += w_f1[i]; np += w_i0[i];
            }
            float npf = (float)np;
            float loc_loss  = (np > 0) ? locsum / (4.0f * fmaxf(npf, 1.0f)) : 0.0f;
            float conf_loss = confsum / (1e-10f + npf);
            float total = conf_loss + loc_loss;
            if (out_size > 0) out[0] = total;
            if (out_size > 1) out[1] = conf_loss;
            if (out_size > 2) out[2] = loc_loss;
            g_ctr = 0u;    // reset for next graph replay
        }
        if (tid < BB && 3 + tid < out_size) out[3 + tid] = (float)g_npos[tid];
        for (int i = 3 + BB + tid; i < out_size; i += TPB) out[i] = 0.0f;
    }
}

extern "C" void kernel_launch(void* const* d_in, const int* in_sizes, int n_in,
                              void* d_out, int out_size) {
    const float* locs   = (const float*)d_in[0];   // (128,8732,4) f32
    const float* scores = (const float*)d_in[1];   // (128,8732,3) f32
    const float* boxes  = (const float*)d_in[2];   // (128,16,4)   f32
    const int*   labels = (const int*)d_in[3];     // (128,16)     i32
    const float* priors = (const float*)d_in[4];   // (8732,4)     f32

    multibox_kernel<<<BB, TPB>>>(locs, scores, boxes, labels, priors,
                                 (float*)d_out, out_size);
}